// round 3
// baseline (speedup 1.0000x reference)
#include <cuda_runtime.h>
#include <math.h>
#include <stdint.h>

// Problem constants
static constexpr int T_   = 512;
static constexpr int B_   = 32;
static constexpr int H_   = 1024;
static constexpr int G4_  = 4096;   // 4*H
static constexpr int NL_  = 5;
static constexpr int NBLK = 128;    // persistent grid size

// ---------------- scratch (device globals; no allocations allowed) ----------
__device__ float g_seq0[(size_t)T_ * B_ * H_];    // layer-0 input (embeddings)
__device__ float g_seq1[(size_t)T_ * B_ * H_];    // layer-0 output / layer-1 input
__device__ float g_gates[(size_t)T_ * B_ * G4_];  // precomputed x@Wih^T + b
__device__ float g_h0[B_ * H_];
__device__ float g_h1[B_ * H_];
__device__ float g_c[B_ * H_];
__device__ unsigned int g_bar_count = 0;
__device__ unsigned int g_bar_gen   = 0;

// ---------------- embedding gather ------------------------------------------
__global__ void embed_k(const int* __restrict__ x, const float* __restrict__ emb) {
    int tb = blockIdx.x;            // tb = t*B + b  (time-major)
    int t = tb / B_;
    int b = tb % B_;
    int tok = x[b * T_ + t];        // x is [B, T]
    const float4* src = (const float4*)(emb + (size_t)tok * H_);
    float4* dst = (float4*)(g_seq0 + (size_t)tb * H_);
    dst[threadIdx.x] = src[threadIdx.x];
}

// ---------------- input GEMM: C[M,4096] = A[M,1024] @ W[4096,1024]^T + bias --
__global__ __launch_bounds__(256, 2)
void gemm_in_k(const float* __restrict__ A, const float* __restrict__ W,
               const float* __restrict__ bias, float* __restrict__ C) {
    __shared__ float As[16][128];
    __shared__ float Bs[16][128];

    const int tid = threadIdx.x;
    const int m0 = blockIdx.y * 128;
    const int n0 = blockIdx.x * 128;
    const int tx = tid & 15;
    const int ty = tid >> 4;
    const int lRow = tid >> 1;
    const int lCol = (tid & 1) * 8;

    const float* Ap = A + (size_t)(m0 + lRow) * 1024 + lCol;
    const float* Wp = W + (size_t)(n0 + lRow) * 1024 + lCol;

    float acc[8][8];
#pragma unroll
    for (int i = 0; i < 8; i++)
#pragma unroll
        for (int j = 0; j < 8; j++) acc[i][j] = 0.f;

    float4 a0 = *(const float4*)(Ap);
    float4 a1 = *(const float4*)(Ap + 4);
    float4 w0 = *(const float4*)(Wp);
    float4 w1 = *(const float4*)(Wp + 4);

    for (int kt = 0; kt < 1024; kt += 16) {
        As[lCol + 0][lRow] = a0.x; As[lCol + 1][lRow] = a0.y;
        As[lCol + 2][lRow] = a0.z; As[lCol + 3][lRow] = a0.w;
        As[lCol + 4][lRow] = a1.x; As[lCol + 5][lRow] = a1.y;
        As[lCol + 6][lRow] = a1.z; As[lCol + 7][lRow] = a1.w;
        Bs[lCol + 0][lRow] = w0.x; Bs[lCol + 1][lRow] = w0.y;
        Bs[lCol + 2][lRow] = w0.z; Bs[lCol + 3][lRow] = w0.w;
        Bs[lCol + 4][lRow] = w1.x; Bs[lCol + 5][lRow] = w1.y;
        Bs[lCol + 6][lRow] = w1.z; Bs[lCol + 7][lRow] = w1.w;
        __syncthreads();

        if (kt + 16 < 1024) {
            a0 = *(const float4*)(Ap + kt + 16);
            a1 = *(const float4*)(Ap + kt + 20);
            w0 = *(const float4*)(Wp + kt + 16);
            w1 = *(const float4*)(Wp + kt + 20);
        }

#pragma unroll
        for (int k = 0; k < 16; k++) {
            float4 x0 = *(const float4*)&As[k][ty * 8];
            float4 x1 = *(const float4*)&As[k][ty * 8 + 4];
            float4 y0 = *(const float4*)&Bs[k][tx * 8];
            float4 y1 = *(const float4*)&Bs[k][tx * 8 + 4];
            float xa[8] = {x0.x, x0.y, x0.z, x0.w, x1.x, x1.y, x1.z, x1.w};
            float yb[8] = {y0.x, y0.y, y0.z, y0.w, y1.x, y1.y, y1.z, y1.w};
#pragma unroll
            for (int i = 0; i < 8; i++)
#pragma unroll
                for (int j = 0; j < 8; j++) acc[i][j] += xa[i] * yb[j];
        }
        __syncthreads();
    }

    float bv[8];
#pragma unroll
    for (int j = 0; j < 8; j++) bv[j] = bias[n0 + tx * 8 + j];
#pragma unroll
    for (int i = 0; i < 8; i++) {
        size_t off = (size_t)(m0 + ty * 8 + i) * G4_ + n0 + tx * 8;
#pragma unroll
        for (int j = 0; j < 8; j++) C[off + j] = acc[i][j] + bv[j];
    }
}

// ---------------- grid barrier for the persistent kernel --------------------
__device__ __forceinline__ void grid_barrier() {
    __syncthreads();
    if (threadIdx.x == 0) {
        __threadfence();
        unsigned g = *((volatile unsigned*)&g_bar_gen);
        unsigned arrived = atomicAdd(&g_bar_count, 1u) + 1u;
        if (arrived == (unsigned)NBLK) {
            g_bar_count = 0;
            __threadfence();
            atomicAdd(&g_bar_gen, 1u);   // release
        } else {
            while (*((volatile unsigned*)&g_bar_gen) == g) { __nanosleep(64); }
        }
    }
    __syncthreads();
}

// ---------------- persistent recurrence (whole layer, one launch) -----------
// 128 blocks x 256 threads; block owns 8 hidden units. Double-buffered h:
// step t reads hbuf[t&1], writes hbuf[(t+1)&1]; one grid barrier per step.
static constexpr int HS_ELEMS = 4 * 64 * 32;   // [ks][kk(64)][b/r(32)]
static constexpr int STEP_SMEM_BYTES = (2 * HS_ELEMS + 32 * 32) * 4;  // 69632 B

__global__ __launch_bounds__(256)
void lstm_persist_k(const float* __restrict__ Whh,
                    const float* __restrict__ gates,
                    float* __restrict__ seq_out) {
    extern __shared__ float sm[];
    float* hs = sm;                 // [4][64][32]
    float* ws = sm + HS_ELEMS;      // [4][64][32]
    float* gf = sm + 2 * HS_ELEMS;  // [32 rows][32 batch]

    const int tid = threadIdx.x;
    const int j0 = blockIdx.x * 8;

    // zero this block's state slice (columns j0..j0+7, all batches)
    {
        int u = tid >> 5, b = tid & 31;
        g_h0[b * H_ + j0 + u] = 0.f;
        g_h1[b * H_ + j0 + u] = 0.f;
        g_c [b * H_ + j0 + u] = 0.f;
    }
    grid_barrier();

    const int ks = tid >> 6;            // k-chunk 0..3
    const int lane = tid & 63;
    const int rr = (lane & 7) * 4;      // 4 gate rows
    const int bb = (lane >> 3) * 4;     // 4 batches

    for (int t = 0; t < T_; t++) {
        const float* hbuf = (t & 1) ? g_h1 : g_h0;
        float*       hout = (t & 1) ? g_h0 : g_h1;
        const float* gates_t = gates + (size_t)t * B_ * G4_;

        // init gf with precomputed input-gate contributions
        for (int i = tid; i < 32 * 32; i += 256) {
            int r = i >> 5, b = i & 31;
            int row = (r >> 3) * H_ + j0 + (r & 7);
            gf[i] = gates_t[(size_t)b * G4_ + row];
        }

        float acc[4][4];
#pragma unroll
        for (int i = 0; i < 4; i++)
#pragma unroll
            for (int j = 0; j < 4; j++) acc[i][j] = 0.f;

        for (int it = 0; it < 4; it++) {
            __syncthreads();
            const int kbase = it * 64;
#pragma unroll
            for (int v = 0; v < 8; v++) {
                int f = v * 256 + tid;
                int ks2 = f >> 9;
                int rem = f & 511;
                int b = rem >> 4;
                int kf = rem & 15;
                // h: cross-SM producer within this kernel -> L2-scope load
                float4 hv = __ldcg((const float4*)(hbuf + b * H_ + ks2 * 256 + kbase + kf * 4));
                float* dh = hs + ks2 * 2048 + (kf * 4) * 32 + b;
                dh[0] = hv.x; dh[32] = hv.y; dh[64] = hv.z; dh[96] = hv.w;
                int row = (b >> 3) * H_ + j0 + (b & 7);
                // Whh: constant across steps -> normal load, becomes L1-resident
                float4 wv = *(const float4*)(Whh + (size_t)row * H_ + ks2 * 256 + kbase + kf * 4);
                float* dw = ws + ks2 * 2048 + (kf * 4) * 32 + b;
                dw[0] = wv.x; dw[32] = wv.y; dw[64] = wv.z; dw[96] = wv.w;
            }
            __syncthreads();

            const float* hb = hs + ks * 2048;
            const float* wb = ws + ks * 2048;
#pragma unroll 8
            for (int kk = 0; kk < 64; kk++) {
                float4 w4 = *(const float4*)(wb + kk * 32 + rr);
                float4 h4 = *(const float4*)(hb + kk * 32 + bb);
                acc[0][0] += w4.x * h4.x; acc[0][1] += w4.x * h4.y;
                acc[0][2] += w4.x * h4.z; acc[0][3] += w4.x * h4.w;
                acc[1][0] += w4.y * h4.x; acc[1][1] += w4.y * h4.y;
                acc[1][2] += w4.y * h4.z; acc[1][3] += w4.y * h4.w;
                acc[2][0] += w4.z * h4.x; acc[2][1] += w4.z * h4.y;
                acc[2][2] += w4.z * h4.z; acc[2][3] += w4.z * h4.w;
                acc[3][0] += w4.w * h4.x; acc[3][1] += w4.w * h4.y;
                acc[3][2] += w4.w * h4.z; acc[3][3] += w4.w * h4.w;
            }
        }

        // reduce the 4 k-chunks into gf
#pragma unroll
        for (int i = 0; i < 4; i++)
#pragma unroll
            for (int j = 0; j < 4; j++)
                atomicAdd(&gf[(rr + i) * 32 + (bb + j)], acc[i][j]);
        __syncthreads();

        // elementwise LSTM update: 8 units x 32 batches = 256 tasks
        {
            int u = tid >> 5;
            int b = tid & 31;
            float iv = gf[(0  + u) * 32 + b];
            float fv = gf[(8  + u) * 32 + b];
            float gv = gf[(16 + u) * 32 + b];
            float ov = gf[(24 + u) * 32 + b];
            int j = j0 + u;
            float c_old = g_c[b * H_ + j];
            float si = 1.f / (1.f + expf(-iv));
            float sf = 1.f / (1.f + expf(-fv));
            float so = 1.f / (1.f + expf(-ov));
            float tg = tanhf(gv);
            float cn = sf * c_old + si * tg;
            float hn = so * tanhf(cn);
            g_c[b * H_ + j] = cn;
            hout[b * H_ + j] = hn;
            if (seq_out) seq_out[(size_t)t * B_ * H_ + b * H_ + j] = hn;
        }

        grid_barrier();   // h(t) fully written before step t+1 reads it
    }
}

// ---------------- head: logits + log_softmax + NLL loss ----------------------
// final h lives in g_h0 (T=512 even: last step t=511 writes buffer 0)
__global__ void head_k(const float* __restrict__ fcW, const float* __restrict__ fcb,
                       const int* __restrict__ labels, float* __restrict__ out,
                       int out_size) {
    __shared__ float lg[B_ * NL_];
    __shared__ float lsum[B_];
    int tid = threadIdx.x;

    if (tid < B_ * NL_) {
        int b = tid / NL_, n = tid % NL_;
        const float4* h4 = (const float4*)(g_h0 + b * H_);
        const float4* w4 = (const float4*)(fcW + n * H_);
        float s = 0.f;
        for (int k = 0; k < H_ / 4; k++) {
            float4 a = h4[k], w = w4[k];
            s += a.x * w.x + a.y * w.y + a.z * w.z + a.w * w.w;
        }
        lg[tid] = s + fcb[n];
    }
    __syncthreads();

    if (tid < B_) {
        float m = -1e30f;
        for (int n = 0; n < NL_; n++) m = fmaxf(m, lg[tid * NL_ + n]);
        float se = 0.f;
        for (int n = 0; n < NL_; n++) se += expf(lg[tid * NL_ + n] - m);
        float lse = m + logf(se);
        int lab = labels[tid];
        lsum[tid] = -(lg[tid * NL_ + lab] - lse);
    }
    __syncthreads();

    if (tid == 0) {
        float L = 0.f;
        for (int b = 0; b < B_; b++) L += lsum[b];
        L /= (float)B_;
        if (out_size >= 1 + B_ * NL_) {
            out[0] = L;
            for (int i = 0; i < B_ * NL_; i++) out[1 + i] = lg[i];
            for (int i = 1 + B_ * NL_; i < out_size; i++) out[i] = 0.f;
        } else if (out_size == B_ * NL_) {
            for (int i = 0; i < B_ * NL_; i++) out[i] = lg[i];
        } else if (out_size >= 1) {
            out[0] = L;
            for (int i = 1; i < out_size; i++) out[i] = 0.f;
        }
    }
}

// ---------------- launch -----------------------------------------------------
extern "C" void kernel_launch(void* const* d_in, const int* in_sizes, int n_in,
                              void* d_out, int out_size) {
    const int*   x      = (const int*)  d_in[0];
    const int*   labels = (const int*)  d_in[1];
    const float* emb    = (const float*)d_in[2];
    const float* Wih    = (const float*)d_in[3];   // [2, 4096, 1024]
    const float* Whh    = (const float*)d_in[4];   // [2, 4096, 1024]
    const float* bias   = (const float*)d_in[5];   // [2, 4096]
    const float* fcW    = (const float*)d_in[6];   // [5, 1024]
    const float* fcb    = (const float*)d_in[7];   // [5]

    cudaFuncSetAttribute(lstm_persist_k, cudaFuncAttributeMaxDynamicSharedMemorySize,
                         STEP_SMEM_BYTES);

    float *seq0, *seq1, *gates;
    cudaGetSymbolAddress((void**)&seq0,  g_seq0);
    cudaGetSymbolAddress((void**)&seq1,  g_seq1);
    cudaGetSymbolAddress((void**)&gates, g_gates);

    // 1. embed -> g_seq0 (time-major [T, B, H])
    embed_k<<<T_ * B_, 256>>>(x, emb);

    for (int l = 0; l < 2; l++) {
        const float* A = (l == 0) ? seq0 : seq1;
        // 2. input GEMM: gates[t,b,:] = seq[t,b,:] @ Wih[l]^T + b[l]
        gemm_in_k<<<dim3(G4_ / 128, (T_ * B_) / 128), 256>>>(
            A, Wih + (size_t)l * G4_ * H_, bias + (size_t)l * G4_, gates);
        // 3. whole-layer persistent recurrence (1 launch, internal grid barrier)
        float* seq_out = (l == 0) ? seq1 : nullptr;
        lstm_persist_k<<<NBLK, 256, STEP_SMEM_BYTES>>>(
            Whh + (size_t)l * G4_ * H_, gates, seq_out);
    }

    // 4. head
    head_k<<<1, 256>>>(fcW, fcb, labels, (float*)d_out, out_size);
}

// round 9
// speedup vs baseline: 1.0968x; 1.0968x over previous
#include <cuda_runtime.h>
#include <cuda_bf16.h>
#include <math.h>
#include <stdint.h>

// Problem constants
static constexpr int T_   = 512;
static constexpr int B_   = 32;
static constexpr int H_   = 1024;
static constexpr int G4_  = 4096;   // 4*H
static constexpr int NL_  = 5;
static constexpr int NBLK = 128;    // persistent grid size

// ---------------- scratch (device globals; no allocations allowed) ----------
__device__ float g_seq0[(size_t)T_ * B_ * H_];    // layer-0 input (embeddings)
__device__ float g_seq1[(size_t)T_ * B_ * H_];    // layer-0 output / layer-1 input
__device__ float g_gates[(size_t)T_ * B_ * G4_];  // precomputed x@Wih^T + b
__device__ float g_h0[B_ * H_];
__device__ float g_h1[B_ * H_];
__device__ float g_c[B_ * H_];
__device__ unsigned int g_bar_count = 0;
__device__ unsigned int g_bar_gen   = 0;
// split-bf16 operands
__device__ __nv_bfloat16 g_Ah[(size_t)T_ * B_ * H_];       // 32 MB
__device__ __nv_bfloat16 g_Al[(size_t)T_ * B_ * H_];       // 32 MB
__device__ __nv_bfloat16 g_Wh[(size_t)2 * G4_ * H_];       // 16 MB
__device__ __nv_bfloat16 g_Wl[(size_t)2 * G4_ * H_];       // 16 MB

__device__ __forceinline__ uint32_t smem_u32(const void* p) {
    uint32_t a;
    asm("{ .reg .u64 t; cvta.to.shared.u64 t, %1; cvt.u32.u64 %0, t; }" : "=r"(a) : "l"(p));
    return a;
}

// ---------------- embedding gather ------------------------------------------
__global__ void embed_k(const int* __restrict__ x, const float* __restrict__ emb) {
    int tb = blockIdx.x;            // tb = t*B + b  (time-major)
    int t = tb / B_;
    int b = tb % B_;
    int tok = x[b * T_ + t];        // x is [B, T]
    const float4* src = (const float4*)(emb + (size_t)tok * H_);
    float4* dst = (float4*)(g_seq0 + (size_t)tb * H_);
    dst[threadIdx.x] = src[threadIdx.x];
}

// ---------------- fp32 -> bf16 (hi, lo) split -------------------------------
__global__ void split_bf16_k(const float* __restrict__ src,
                             __nv_bfloat16* __restrict__ hi,
                             __nv_bfloat16* __restrict__ lo, int n4) {
    int i = blockIdx.x * blockDim.x + threadIdx.x;
    if (i >= n4) return;
    float4 v = ((const float4*)src)[i];
    __nv_bfloat16 h0 = __float2bfloat16(v.x);
    __nv_bfloat16 h1 = __float2bfloat16(v.y);
    __nv_bfloat16 h2 = __float2bfloat16(v.z);
    __nv_bfloat16 h3 = __float2bfloat16(v.w);
    __nv_bfloat16 l0 = __float2bfloat16(v.x - __bfloat162float(h0));
    __nv_bfloat16 l1 = __float2bfloat16(v.y - __bfloat162float(h1));
    __nv_bfloat16 l2 = __float2bfloat16(v.z - __bfloat162float(h2));
    __nv_bfloat16 l3 = __float2bfloat16(v.w - __bfloat162float(h3));
    __nv_bfloat162* hp = (__nv_bfloat162*)hi;
    __nv_bfloat162* lp = (__nv_bfloat162*)lo;
    hp[2 * i]     = __nv_bfloat162(h0, h1);
    hp[2 * i + 1] = __nv_bfloat162(h2, h3);
    lp[2 * i]     = __nv_bfloat162(l0, l1);
    lp[2 * i + 1] = __nv_bfloat162(l2, l3);
}

// ---------------- mma.sync split-bf16 GEMM ----------------------------------
// C[16384,4096] = A[16384,1024] @ W[4096,1024]^T + bias, via 3 bf16 products.
// Block tile 128x128, BK=64, 8 warps (2m x 4n), warp tile 64x32.
// Smem tiles swizzled: unit' = unit ^ (row & 7)  (rows of 8 x 16B units).
__device__ __forceinline__ void mma16816(float* c, const uint32_t* a, const uint32_t* b) {
    asm volatile(
        "mma.sync.aligned.m16n8k16.row.col.f32.bf16.bf16.f32 "
        "{%0,%1,%2,%3}, {%4,%5,%6,%7}, {%8,%9}, {%0,%1,%2,%3};"
        : "+f"(c[0]), "+f"(c[1]), "+f"(c[2]), "+f"(c[3])
        : "r"(a[0]), "r"(a[1]), "r"(a[2]), "r"(a[3]), "r"(b[0]), "r"(b[1]));
}

__global__ __launch_bounds__(256)
void gemm_mma_k(const __nv_bfloat16* __restrict__ Ah, const __nv_bfloat16* __restrict__ Al,
                const __nv_bfloat16* __restrict__ Wh, const __nv_bfloat16* __restrict__ Wl,
                const float* __restrict__ bias, float* __restrict__ C) {
    __shared__ __nv_bfloat16 As[128 * 64];   // 16 KB, swizzled
    __shared__ __nv_bfloat16 Ws[128 * 64];   // 16 KB, swizzled

    const int tid  = threadIdx.x;
    const int warp = tid >> 5;
    const int lane = tid & 31;
    const int wm = warp >> 2;        // 0..1 -> m offset wm*64
    const int wn = warp & 3;         // 0..3 -> n offset wn*32
    const int m0 = blockIdx.y * 128;
    const int n0 = blockIdx.x * 128;

    const __nv_bfloat16* srcA[3] = {Ah, Ah, Al};
    const __nv_bfloat16* srcW[3] = {Wh, Wl, Wh};

    // per-thread load geometry (identical for A and W tiles: 128 rows x 8 units)
    int rowL[4], uL[4], dstL[4];
#pragma unroll
    for (int i = 0; i < 4; i++) {
        int idx = i * 256 + tid;          // 0..1023
        rowL[i] = idx >> 3;
        uL[i]   = idx & 7;
        dstL[i] = rowL[i] * 64 + ((uL[i] ^ (rowL[i] & 7)) << 3);   // in bf16 elems
    }

    float acc[4][4][4];
#pragma unroll
    for (int mt = 0; mt < 4; mt++)
#pragma unroll
        for (int nt = 0; nt < 4; nt++)
#pragma unroll
            for (int q = 0; q < 4; q++) acc[mt][nt][q] = 0.f;

    // ldmatrix row indices (constant per thread)
    int lrowA[4], lrowB[4];
#pragma unroll
    for (int mt = 0; mt < 4; mt++) lrowA[mt] = wm * 64 + mt * 16 + (lane & 15);
#pragma unroll
    for (int nt = 0; nt < 4; nt++) lrowB[nt] = wn * 32 + nt * 8 + (lane & 7);
    const uint32_t a_base = smem_u32(As);
    const uint32_t w_base = smem_u32(Ws);

    float4 pa[4], pw[4];
    // prefetch iteration 0
#pragma unroll
    for (int i = 0; i < 4; i++) {
        pa[i] = *(const float4*)(srcA[0] + (size_t)(m0 + rowL[i]) * H_ + uL[i] * 8);
        pw[i] = *(const float4*)(srcW[0] + (size_t)(n0 + rowL[i]) * H_ + uL[i] * 8);
    }

    for (int it = 0; it < 48; it++) {
#pragma unroll
        for (int i = 0; i < 4; i++) {
            *(float4*)(As + dstL[i]) = pa[i];
            *(float4*)(Ws + dstL[i]) = pw[i];
        }
        __syncthreads();

        if (it + 1 < 48) {
            int p2 = (it + 1) >> 4;
            int kcol2 = ((it + 1) & 15) * 64;
#pragma unroll
            for (int i = 0; i < 4; i++) {
                pa[i] = *(const float4*)(srcA[p2] + (size_t)(m0 + rowL[i]) * H_ + kcol2 + uL[i] * 8);
                pw[i] = *(const float4*)(srcW[p2] + (size_t)(n0 + rowL[i]) * H_ + kcol2 + uL[i] * 8);
            }
        }

#pragma unroll
        for (int ks = 0; ks < 4; ks++) {
            uint32_t af[4][4], bf[4][2];
            int ua = ks * 2 + (lane >> 4);
#pragma unroll
            for (int mt = 0; mt < 4; mt++) {
                uint32_t addr = a_base + (uint32_t)(lrowA[mt] * 128 + ((ua ^ (lrowA[mt] & 7)) << 4));
                asm volatile("ldmatrix.sync.aligned.m8n8.x4.shared.b16 {%0,%1,%2,%3}, [%4];"
                             : "=r"(af[mt][0]), "=r"(af[mt][1]), "=r"(af[mt][2]), "=r"(af[mt][3])
                             : "r"(addr));
            }
            int ub = ks * 2 + ((lane >> 3) & 1);
#pragma unroll
            for (int nt = 0; nt < 4; nt++) {
                uint32_t addr = w_base + (uint32_t)(lrowB[nt] * 128 + ((ub ^ (lrowB[nt] & 7)) << 4));
                asm volatile("ldmatrix.sync.aligned.m8n8.x2.shared.b16 {%0,%1}, [%2];"
                             : "=r"(bf[nt][0]), "=r"(bf[nt][1])
                             : "r"(addr));
            }
#pragma unroll
            for (int mt = 0; mt < 4; mt++)
#pragma unroll
                for (int nt = 0; nt < 4; nt++)
                    mma16816(acc[mt][nt], af[mt], bf[nt]);
        }
        __syncthreads();
    }

    // epilogue: fragment layout -> gmem with bias
    const int qr = lane >> 2;            // row within tile
    const int qc = (lane & 3) * 2;       // col pair within 8
#pragma unroll
    for (int mt = 0; mt < 4; mt++) {
        int rm = m0 + wm * 64 + mt * 16 + qr;
#pragma unroll
        for (int nt = 0; nt < 4; nt++) {
            int cb = n0 + wn * 32 + nt * 8 + qc;
            float b0 = bias[cb], b1 = bias[cb + 1];
            *(float2*)(C + (size_t)rm * G4_ + cb) =
                make_float2(acc[mt][nt][0] + b0, acc[mt][nt][1] + b1);
            *(float2*)(C + (size_t)(rm + 8) * G4_ + cb) =
                make_float2(acc[mt][nt][2] + b0, acc[mt][nt][3] + b1);
        }
    }
}

// ---------------- grid barrier for the persistent kernel --------------------
__device__ __forceinline__ void grid_barrier() {
    __syncthreads();
    if (threadIdx.x == 0) {
        __threadfence();
        unsigned g = *((volatile unsigned*)&g_bar_gen);
        unsigned arrived = atomicAdd(&g_bar_count, 1u) + 1u;
        if (arrived == (unsigned)NBLK) {
            g_bar_count = 0;
            __threadfence();
            atomicAdd(&g_bar_gen, 1u);   // release
        } else {
            while (*((volatile unsigned*)&g_bar_gen) == g) { __nanosleep(64); }
        }
    }
    __syncthreads();
}

// ---------------- persistent recurrence (whole layer, one launch) -----------
static constexpr int HS_ELEMS = 4 * 64 * 32;   // [ks][kk(64)][b/r(32)]
static constexpr int STEP_SMEM_BYTES = (2 * HS_ELEMS + 32 * 32) * 4;  // 69632 B

__global__ __launch_bounds__(256)
void lstm_persist_k(const float* __restrict__ Whh,
                    const float* __restrict__ gates,
                    float* __restrict__ seq_out) {
    extern __shared__ float sm[];
    float* hs = sm;                 // [4][64][32]
    float* ws = sm + HS_ELEMS;      // [4][64][32]
    float* gf = sm + 2 * HS_ELEMS;  // [32 rows][32 batch]

    const int tid = threadIdx.x;
    const int j0 = blockIdx.x * 8;

    {
        int u = tid >> 5, b = tid & 31;
        g_h0[b * H_ + j0 + u] = 0.f;
        g_h1[b * H_ + j0 + u] = 0.f;
        g_c [b * H_ + j0 + u] = 0.f;
    }
    grid_barrier();

    const int ks = tid >> 6;            // k-chunk 0..3
    const int lane = tid & 63;
    const int rr = (lane & 7) * 4;      // 4 gate rows
    const int bb = (lane >> 3) * 4;     // 4 batches

    for (int t = 0; t < T_; t++) {
        const float* hbuf = (t & 1) ? g_h1 : g_h0;
        float*       hout = (t & 1) ? g_h0 : g_h1;
        const float* gates_t = gates + (size_t)t * B_ * G4_;

        for (int i = tid; i < 32 * 32; i += 256) {
            int r = i >> 5, b = i & 31;
            int row = (r >> 3) * H_ + j0 + (r & 7);
            gf[i] = gates_t[(size_t)b * G4_ + row];
        }

        float acc[4][4];
#pragma unroll
        for (int i = 0; i < 4; i++)
#pragma unroll
            for (int j = 0; j < 4; j++) acc[i][j] = 0.f;

        for (int it = 0; it < 4; it++) {
            __syncthreads();
            const int kbase = it * 64;
#pragma unroll
            for (int v = 0; v < 8; v++) {
                int f = v * 256 + tid;
                int ks2 = f >> 9;
                int rem = f & 511;
                int b = rem >> 4;
                int kf = rem & 15;
                float4 hv = __ldcg((const float4*)(hbuf + b * H_ + ks2 * 256 + kbase + kf * 4));
                float* dh = hs + ks2 * 2048 + (kf * 4) * 32 + b;
                dh[0] = hv.x; dh[32] = hv.y; dh[64] = hv.z; dh[96] = hv.w;
                int row = (b >> 3) * H_ + j0 + (b & 7);
                float4 wv = *(const float4*)(Whh + (size_t)row * H_ + ks2 * 256 + kbase + kf * 4);
                float* dw = ws + ks2 * 2048 + (kf * 4) * 32 + b;
                dw[0] = wv.x; dw[32] = wv.y; dw[64] = wv.z; dw[96] = wv.w;
            }
            __syncthreads();

            const float* hb = hs + ks * 2048;
            const float* wb = ws + ks * 2048;
#pragma unroll 8
            for (int kk = 0; kk < 64; kk++) {
                float4 w4 = *(const float4*)(wb + kk * 32 + rr);
                float4 h4 = *(const float4*)(hb + kk * 32 + bb);
                acc[0][0] += w4.x * h4.x; acc[0][1] += w4.x * h4.y;
                acc[0][2] += w4.x * h4.z; acc[0][3] += w4.x * h4.w;
                acc[1][0] += w4.y * h4.x; acc[1][1] += w4.y * h4.y;
                acc[1][2] += w4.y * h4.z; acc[1][3] += w4.y * h4.w;
                acc[2][0] += w4.z * h4.x; acc[2][1] += w4.z * h4.y;
                acc[2][2] += w4.z * h4.z; acc[2][3] += w4.z * h4.w;
                acc[3][0] += w4.w * h4.x; acc[3][1] += w4.w * h4.y;
                acc[3][2] += w4.w * h4.z; acc[3][3] += w4.w * h4.w;
            }
        }

#pragma unroll
        for (int i = 0; i < 4; i++)
#pragma unroll
            for (int j = 0; j < 4; j++)
                atomicAdd(&gf[(rr + i) * 32 + (bb + j)], acc[i][j]);
        __syncthreads();

        {
            int u = tid >> 5;
            int b = tid & 31;
            float iv = gf[(0  + u) * 32 + b];
            float fv = gf[(8  + u) * 32 + b];
            float gv = gf[(16 + u) * 32 + b];
            float ov = gf[(24 + u) * 32 + b];
            int j = j0 + u;
            float c_old = g_c[b * H_ + j];
            float si = 1.f / (1.f + expf(-iv));
            float sf = 1.f / (1.f + expf(-fv));
            float so = 1.f / (1.f + expf(-ov));
            float tg = tanhf(gv);
            float cn = sf * c_old + si * tg;
            float hn = so * tanhf(cn);
            g_c[b * H_ + j] = cn;
            hout[b * H_ + j] = hn;
            if (seq_out) seq_out[(size_t)t * B_ * H_ + b * H_ + j] = hn;
        }

        grid_barrier();
    }
}

// ---------------- head: logits + log_softmax + NLL loss ----------------------
__global__ void head_k(const float* __restrict__ fcW, const float* __restrict__ fcb,
                       const int* __restrict__ labels, float* __restrict__ out,
                       int out_size) {
    __shared__ float lg[B_ * NL_];
    __shared__ float lsum[B_];
    int tid = threadIdx.x;

    if (tid < B_ * NL_) {
        int b = tid / NL_, n = tid % NL_;
        const float4* h4 = (const float4*)(g_h0 + b * H_);
        const float4* w4 = (const float4*)(fcW + n * H_);
        float s = 0.f;
        for (int k = 0; k < H_ / 4; k++) {
            float4 a = h4[k], w = w4[k];
            s += a.x * w.x + a.y * w.y + a.z * w.z + a.w * w.w;
        }
        lg[tid] = s + fcb[n];
    }
    __syncthreads();

    if (tid < B_) {
        float m = -1e30f;
        for (int n = 0; n < NL_; n++) m = fmaxf(m, lg[tid * NL_ + n]);
        float se = 0.f;
        for (int n = 0; n < NL_; n++) se += expf(lg[tid * NL_ + n] - m);
        float lse = m + logf(se);
        int lab = labels[tid];
        lsum[tid] = -(lg[tid * NL_ + lab] - lse);
    }
    __syncthreads();

    if (tid == 0) {
        float L = 0.f;
        for (int b = 0; b < B_; b++) L += lsum[b];
        L /= (float)B_;
        if (out_size >= 1 + B_ * NL_) {
            out[0] = L;
            for (int i = 0; i < B_ * NL_; i++) out[1 + i] = lg[i];
            for (int i = 1 + B_ * NL_; i < out_size; i++) out[i] = 0.f;
        } else if (out_size == B_ * NL_) {
            for (int i = 0; i < B_ * NL_; i++) out[i] = lg[i];
        } else if (out_size >= 1) {
            out[0] = L;
            for (int i = 1; i < out_size; i++) out[i] = 0.f;
        }
    }
}

// ---------------- launch -----------------------------------------------------
extern "C" void kernel_launch(void* const* d_in, const int* in_sizes, int n_in,
                              void* d_out, int out_size) {
    const int*   x      = (const int*)  d_in[0];
    const int*   labels = (const int*)  d_in[1];
    const float* emb    = (const float*)d_in[2];
    const float* Wih    = (const float*)d_in[3];   // [2, 4096, 1024]
    const float* Whh    = (const float*)d_in[4];   // [2, 4096, 1024]
    const float* bias   = (const float*)d_in[5];   // [2, 4096]
    const float* fcW    = (const float*)d_in[6];   // [5, 1024]
    const float* fcb    = (const float*)d_in[7];   // [5]

    cudaFuncSetAttribute(lstm_persist_k, cudaFuncAttributeMaxDynamicSharedMemorySize,
                         STEP_SMEM_BYTES);

    float *seq0, *seq1, *gates;
    __nv_bfloat16 *Ah, *Al, *Wh, *Wl;
    cudaGetSymbolAddress((void**)&seq0,  g_seq0);
    cudaGetSymbolAddress((void**)&seq1,  g_seq1);
    cudaGetSymbolAddress((void**)&gates, g_gates);
    cudaGetSymbolAddress((void**)&Ah, g_Ah);
    cudaGetSymbolAddress((void**)&Al, g_Al);
    cudaGetSymbolAddress((void**)&Wh, g_Wh);
    cudaGetSymbolAddress((void**)&Wl, g_Wl);

    // 0. split both layers' Wih to bf16 hi/lo
    {
        int n4 = 2 * G4_ * H_ / 4;
        split_bf16_k<<<(n4 + 255) / 256, 256>>>(Wih, Wh, Wl, n4);
    }
    // 1. embed -> g_seq0 (time-major [T, B, H])
    embed_k<<<T_ * B_, 256>>>(x, emb);

    for (int l = 0; l < 2; l++) {
        const float* A = (l == 0) ? seq0 : seq1;
        // 2a. split A to bf16 hi/lo
        int n4 = T_ * B_ * H_ / 4;
        split_bf16_k<<<(n4 + 255) / 256, 256>>>(A, Ah, Al, n4);
        // 2b. tensor-core input GEMM (mma.sync; 3 bf16 products, K-folded)
        gemm_mma_k<<<dim3(G4_ / 128, (T_ * B_) / 128), 256>>>(
            Ah, Al, Wh + (size_t)l * G4_ * H_, Wl + (size_t)l * G4_ * H_,
            bias + (size_t)l * G4_, gates);
        // 3. whole-layer persistent recurrence
        float* seq_out = (l == 0) ? seq1 : nullptr;
        lstm_persist_k<<<NBLK, 256, STEP_SMEM_BYTES>>>(
            Whh + (size_t)l * G4_ * H_, gates, seq_out);
    }

    // 4. head
    head_k<<<1, 256>>>(fcW, fcb, labels, (float*)d_out, out_size);
}

// round 10
// speedup vs baseline: 3.9347x; 3.5876x over previous
#include <cuda_runtime.h>
#include <cuda_bf16.h>
#include <math.h>
#include <stdint.h>

// Problem constants
static constexpr int T_   = 512;
static constexpr int B_   = 32;
static constexpr int H_   = 1024;
static constexpr int G4_  = 4096;   // 4*H
static constexpr int NL_  = 5;
static constexpr int NBLK = 128;    // persistent grid size

// ---------------- scratch (device globals; no allocations allowed) ----------
__device__ float g_seq0[(size_t)T_ * B_ * H_];    // layer-0 input (embeddings)
__device__ float g_seq1[(size_t)T_ * B_ * H_];    // layer-0 output / layer-1 input
__device__ float g_gates[(size_t)T_ * B_ * G4_];  // precomputed x@Wih^T + b
__device__ float g_h0[B_ * H_];                   // final h (for head)
__device__ unsigned int g_bar_count = 0;
__device__ unsigned int g_bar_gen   = 0;
// split-bf16 operands (input GEMM)
__device__ __nv_bfloat16 g_Ah[(size_t)T_ * B_ * H_];
__device__ __nv_bfloat16 g_Al[(size_t)T_ * B_ * H_];
__device__ __nv_bfloat16 g_Wh[(size_t)2 * G4_ * H_];
__device__ __nv_bfloat16 g_Wl[(size_t)2 * G4_ * H_];
// split-bf16 recurrent weights
__device__ __nv_bfloat16 g_WhH[(size_t)2 * G4_ * H_];
__device__ __nv_bfloat16 g_WhL[(size_t)2 * G4_ * H_];
// double-buffered bf16 hidden state (hi/lo), [B][H] row-major
__device__ __nv_bfloat16 g_hhA[B_ * H_];
__device__ __nv_bfloat16 g_hlA[B_ * H_];
__device__ __nv_bfloat16 g_hhB[B_ * H_];
__device__ __nv_bfloat16 g_hlB[B_ * H_];

__device__ __forceinline__ uint32_t smem_u32(const void* p) {
    uint32_t a;
    asm("{ .reg .u64 t; cvta.to.shared.u64 t, %1; cvt.u32.u64 %0, t; }" : "=r"(a) : "l"(p));
    return a;
}

__device__ __forceinline__ void mma16816(float* c, const uint32_t* a, const uint32_t* b) {
    asm volatile(
        "mma.sync.aligned.m16n8k16.row.col.f32.bf16.bf16.f32 "
        "{%0,%1,%2,%3}, {%4,%5,%6,%7}, {%8,%9}, {%0,%1,%2,%3};"
        : "+f"(c[0]), "+f"(c[1]), "+f"(c[2]), "+f"(c[3])
        : "r"(a[0]), "r"(a[1]), "r"(a[2]), "r"(a[3]), "r"(b[0]), "r"(b[1]));
}
__device__ __forceinline__ void ldmx4(uint32_t* r, uint32_t addr) {
    asm volatile("ldmatrix.sync.aligned.m8n8.x4.shared.b16 {%0,%1,%2,%3}, [%4];"
                 : "=r"(r[0]), "=r"(r[1]), "=r"(r[2]), "=r"(r[3]) : "r"(addr));
}
__device__ __forceinline__ void ldmx2(uint32_t* r, uint32_t addr) {
    asm volatile("ldmatrix.sync.aligned.m8n8.x2.shared.b16 {%0,%1}, [%2];"
                 : "=r"(r[0]), "=r"(r[1]) : "r"(addr));
}

// ---------------- embedding gather ------------------------------------------
__global__ void embed_k(const int* __restrict__ x, const float* __restrict__ emb) {
    int tb = blockIdx.x;
    int t = tb / B_;
    int b = tb % B_;
    int tok = x[b * T_ + t];
    const float4* src = (const float4*)(emb + (size_t)tok * H_);
    float4* dst = (float4*)(g_seq0 + (size_t)tb * H_);
    dst[threadIdx.x] = src[threadIdx.x];
}

// ---------------- fp32 -> bf16 (hi, lo) split -------------------------------
__global__ void split_bf16_k(const float* __restrict__ src,
                             __nv_bfloat16* __restrict__ hi,
                             __nv_bfloat16* __restrict__ lo, int n4) {
    int i = blockIdx.x * blockDim.x + threadIdx.x;
    if (i >= n4) return;
    float4 v = ((const float4*)src)[i];
    __nv_bfloat16 h0 = __float2bfloat16(v.x);
    __nv_bfloat16 h1 = __float2bfloat16(v.y);
    __nv_bfloat16 h2 = __float2bfloat16(v.z);
    __nv_bfloat16 h3 = __float2bfloat16(v.w);
    __nv_bfloat16 l0 = __float2bfloat16(v.x - __bfloat162float(h0));
    __nv_bfloat16 l1 = __float2bfloat16(v.y - __bfloat162float(h1));
    __nv_bfloat16 l2 = __float2bfloat16(v.z - __bfloat162float(h2));
    __nv_bfloat16 l3 = __float2bfloat16(v.w - __bfloat162float(h3));
    __nv_bfloat162* hp = (__nv_bfloat162*)hi;
    __nv_bfloat162* lp = (__nv_bfloat162*)lo;
    hp[2 * i]     = __nv_bfloat162(h0, h1);
    hp[2 * i + 1] = __nv_bfloat162(h2, h3);
    lp[2 * i]     = __nv_bfloat162(l0, l1);
    lp[2 * i + 1] = __nv_bfloat162(l2, l3);
}

// ---------------- mma.sync split-bf16 input GEMM (unchanged from R9) --------
__global__ __launch_bounds__(256)
void gemm_mma_k(const __nv_bfloat16* __restrict__ Ah, const __nv_bfloat16* __restrict__ Al,
                const __nv_bfloat16* __restrict__ Wh, const __nv_bfloat16* __restrict__ Wl,
                const float* __restrict__ bias, float* __restrict__ C) {
    __shared__ __nv_bfloat16 As[128 * 64];
    __shared__ __nv_bfloat16 Ws[128 * 64];

    const int tid  = threadIdx.x;
    const int warp = tid >> 5;
    const int lane = tid & 31;
    const int wm = warp >> 2;
    const int wn = warp & 3;
    const int m0 = blockIdx.y * 128;
    const int n0 = blockIdx.x * 128;

    const __nv_bfloat16* srcA[3] = {Ah, Ah, Al};
    const __nv_bfloat16* srcW[3] = {Wh, Wl, Wh};

    int rowL[4], uL[4], dstL[4];
#pragma unroll
    for (int i = 0; i < 4; i++) {
        int idx = i * 256 + tid;
        rowL[i] = idx >> 3;
        uL[i]   = idx & 7;
        dstL[i] = rowL[i] * 64 + ((uL[i] ^ (rowL[i] & 7)) << 3);
    }

    float acc[4][4][4];
#pragma unroll
    for (int mt = 0; mt < 4; mt++)
#pragma unroll
        for (int nt = 0; nt < 4; nt++)
#pragma unroll
            for (int q = 0; q < 4; q++) acc[mt][nt][q] = 0.f;

    int lrowA[4], lrowB[4];
#pragma unroll
    for (int mt = 0; mt < 4; mt++) lrowA[mt] = wm * 64 + mt * 16 + (lane & 15);
#pragma unroll
    for (int nt = 0; nt < 4; nt++) lrowB[nt] = wn * 32 + nt * 8 + (lane & 7);
    const uint32_t a_base = smem_u32(As);
    const uint32_t w_base = smem_u32(Ws);

    float4 pa[4], pw[4];
#pragma unroll
    for (int i = 0; i < 4; i++) {
        pa[i] = *(const float4*)(srcA[0] + (size_t)(m0 + rowL[i]) * H_ + uL[i] * 8);
        pw[i] = *(const float4*)(srcW[0] + (size_t)(n0 + rowL[i]) * H_ + uL[i] * 8);
    }

    for (int it = 0; it < 48; it++) {
#pragma unroll
        for (int i = 0; i < 4; i++) {
            *(float4*)(As + dstL[i]) = pa[i];
            *(float4*)(Ws + dstL[i]) = pw[i];
        }
        __syncthreads();

        if (it + 1 < 48) {
            int p2 = (it + 1) >> 4;
            int kcol2 = ((it + 1) & 15) * 64;
#pragma unroll
            for (int i = 0; i < 4; i++) {
                pa[i] = *(const float4*)(srcA[p2] + (size_t)(m0 + rowL[i]) * H_ + kcol2 + uL[i] * 8);
                pw[i] = *(const float4*)(srcW[p2] + (size_t)(n0 + rowL[i]) * H_ + kcol2 + uL[i] * 8);
            }
        }

#pragma unroll
        for (int ks = 0; ks < 4; ks++) {
            uint32_t af[4][4], bf[4][2];
            int ua = ks * 2 + (lane >> 4);
#pragma unroll
            for (int mt = 0; mt < 4; mt++)
                ldmx4(af[mt], a_base + (uint32_t)(lrowA[mt] * 128 + ((ua ^ (lrowA[mt] & 7)) << 4)));
            int ub = ks * 2 + ((lane >> 3) & 1);
#pragma unroll
            for (int nt = 0; nt < 4; nt++)
                ldmx2(bf[nt], w_base + (uint32_t)(lrowB[nt] * 128 + ((ub ^ (lrowB[nt] & 7)) << 4)));
#pragma unroll
            for (int mt = 0; mt < 4; mt++)
#pragma unroll
                for (int nt = 0; nt < 4; nt++)
                    mma16816(acc[mt][nt], af[mt], bf[nt]);
        }
        __syncthreads();
    }

    const int qr = lane >> 2;
    const int qc = (lane & 3) * 2;
#pragma unroll
    for (int mt = 0; mt < 4; mt++) {
        int rm = m0 + wm * 64 + mt * 16 + qr;
#pragma unroll
        for (int nt = 0; nt < 4; nt++) {
            int cb = n0 + wn * 32 + nt * 8 + qc;
            float b0 = bias[cb], b1 = bias[cb + 1];
            *(float2*)(C + (size_t)rm * G4_ + cb) =
                make_float2(acc[mt][nt][0] + b0, acc[mt][nt][1] + b1);
            *(float2*)(C + (size_t)(rm + 8) * G4_ + cb) =
                make_float2(acc[mt][nt][2] + b0, acc[mt][nt][3] + b1);
        }
    }
}

// ---------------- grid barrier for the persistent kernel --------------------
__device__ __forceinline__ void grid_barrier() {
    __syncthreads();
    if (threadIdx.x == 0) {
        __threadfence();
        unsigned g = *((volatile unsigned*)&g_bar_gen);
        unsigned arrived = atomicAdd(&g_bar_count, 1u) + 1u;
        if (arrived == (unsigned)NBLK) {
            g_bar_count = 0;
            __threadfence();
            atomicAdd(&g_bar_gen, 1u);
        } else {
            while (*((volatile unsigned*)&g_bar_gen) == g) { __nanosleep(64); }
        }
    }
    __syncthreads();
}

// ---------------- tensor-core persistent recurrence --------------------------
// 128 blocks x 256 threads (8 warps). Block owns 8 hidden units = 32 gate rows
// (local row r -> global gate row (r>>3)*1024 + j0 + (r&7)).
// Per step: G[32r][32b] = gates_pre + Whh_slice @ h^T via 3 bf16 products.
// Warps split K 8-ways (128 each); Whh-hi fragments live in REGISTERS
// (loop-invariant), Whh-lo in smem, h staged hi/lo in smem each step.
// Smem tiles: 16 chunks of [32 rows][64 cols] bf16, swizzled like the GEMM.
static constexpr int WL_OFF  = 0;         // 65536 B
static constexpr int HH_OFF  = 65536;     // 65536 B (also Wh staging in prologue)
static constexpr int HL_OFF  = 131072;    // 65536 B
static constexpr int RED_OFF = 196608;    // 8 x 32cols x 34pad x 4B = 34816 B
static constexpr int LSTM_SMEM = 231424;

__global__ __launch_bounds__(256)
void lstm_tc_k(const __nv_bfloat16* __restrict__ WhH,
               const __nv_bfloat16* __restrict__ WhL,
               const float* __restrict__ gates,
               float* __restrict__ seq_out) {
    extern __shared__ char smem[];
    float* red = (float*)(smem + RED_OFF);
    const uint32_t sbase   = smem_u32(smem);
    const uint32_t wl_base = sbase + WL_OFF;
    const uint32_t hh_base = sbase + HH_OFF;
    const uint32_t hl_base = sbase + HL_OFF;

    const int tid  = threadIdx.x;
    const int wid  = tid >> 5;
    const int lane = tid & 31;
    const int j0   = blockIdx.x * 8;

    // zero the global bf16 h buffers (exact cover: 128 blk * 256 thr = 32768)
    {
        int i = blockIdx.x * 256 + tid;
        g_hhA[i] = __nv_bfloat16(0.f); g_hlA[i] = __nv_bfloat16(0.f);
        g_hhB[i] = __nv_bfloat16(0.f); g_hlB[i] = __nv_bfloat16(0.f);
    }

    // ---- prologue: stage Whh hi (into HH area) and lo (into WL area) -------
    // 32 local rows x 1024 cols; 128 float4 per row.
    for (int idx = tid; idx < 32 * 128; idx += 256) {
        int r = idx >> 7, f = idx & 127;
        int grow = (r >> 3) * H_ + j0 + (r & 7);
        int dst = (f >> 3) * 4096 + r * 128 + (((f & 7) ^ (r & 7)) << 4);
        *(float4*)(smem + HH_OFF + dst) = *(const float4*)(WhH + (size_t)grow * H_ + f * 8);
        *(float4*)(smem + WL_OFF + dst) = *(const float4*)(WhL + (size_t)grow * H_ + f * 8);
    }
    __syncthreads();

    // per-warp ldmatrix geometry
    const int lrA0 = (lane & 15);            // + mt*16
    const int lrB0 = (lane & 7);             // + nt*8
    const int kselA = lane >> 4;             // 0/1
    const int kselB = (lane >> 3) & 1;       // 0/1

    // preload Whh-hi fragments: [mt][ks][4] = 64 regs
    uint32_t wh[2][8][4];
#pragma unroll
    for (int mt = 0; mt < 2; mt++)
#pragma unroll
        for (int ks = 0; ks < 8; ks++) {
            int c  = wid * 2 + (ks >> 2);
            int ua = (ks & 3) * 2 + kselA;
            int lr = mt * 16 + lrA0;
            ldmx4(wh[mt][ks], hh_base + (uint32_t)(c * 4096 + lr * 128 + ((ua ^ (lr & 7)) << 4)));
        }
    grid_barrier();   // h zeroing visible; HH smem free for h staging

    float c_reg = 0.f;   // cell state for (unit=wid, batch=lane)

    for (int t = 0; t < T_; t++) {
        const __nv_bfloat16* hhin = (t & 1) ? g_hhB : g_hhA;
        const __nv_bfloat16* hlin = (t & 1) ? g_hlB : g_hlA;
        __nv_bfloat16* hhout = (t & 1) ? g_hhA : g_hhB;
        __nv_bfloat16* hlout = (t & 1) ? g_hlA : g_hlB;
        const float* gates_t = gates + (size_t)t * B_ * G4_;

        // stage gate pre-activations into red[7] (coalesced)
        {
            int b = tid >> 3, q = tid & 7, g = q >> 1, half = q & 1;
            float4 v = *(const float4*)(gates_t + (size_t)b * G4_ + g * H_ + j0 + half * 4);
            float* rp = red + 7 * 1088 + b * 34 + g * 8 + half * 4;
            rp[0] = v.x; rp[1] = v.y; rp[2] = v.z; rp[3] = v.w;
        }
        // stage h hi/lo (bf16 [32][1024] -> swizzled chunk tiles), L2-scope loads
        {
            const float4* hh4 = (const float4*)hhin;
            const float4* hl4 = (const float4*)hlin;
#pragma unroll
            for (int v2 = 0; v2 < 16; v2++) {
                int idx = v2 * 256 + tid;
                int row = idx >> 7, f = idx & 127;
                int dst = (f >> 3) * 4096 + row * 128 + (((f & 7) ^ (row & 7)) << 4);
                *(float4*)(smem + HH_OFF + dst) = __ldcg(hh4 + idx);
                *(float4*)(smem + HL_OFF + dst) = __ldcg(hl4 + idx);
            }
        }
        __syncthreads();

        // ---- MMA phase: 3 products over this warp's K slice ----------------
        float acc[2][4][4];
#pragma unroll
        for (int mt = 0; mt < 2; mt++)
#pragma unroll
            for (int nt = 0; nt < 4; nt++)
#pragma unroll
                for (int q = 0; q < 4; q++) acc[mt][nt][q] = 0.f;

#pragma unroll
        for (int ks = 0; ks < 8; ks++) {
            int c  = wid * 2 + (ks >> 2);
            int klo = (ks & 3) * 2;
            uint32_t al[2][4], bh[4][2], bl[4][2];
#pragma unroll
            for (int mt = 0; mt < 2; mt++) {
                int lr = mt * 16 + lrA0;
                int ua = klo + kselA;
                ldmx4(al[mt], wl_base + (uint32_t)(c * 4096 + lr * 128 + ((ua ^ (lr & 7)) << 4)));
            }
#pragma unroll
            for (int nt = 0; nt < 4; nt++) {
                int lr = nt * 8 + lrB0;
                int ub = klo + kselB;
                uint32_t off = (uint32_t)(c * 4096 + lr * 128 + ((ub ^ (lr & 7)) << 4));
                ldmx2(bh[nt], hh_base + off);
                ldmx2(bl[nt], hl_base + off);
            }
#pragma unroll
            for (int mt = 0; mt < 2; mt++)
#pragma unroll
                for (int nt = 0; nt < 4; nt++) {
                    mma16816(acc[mt][nt], wh[mt][ks], bh[nt]);   // wh*hh
                    mma16816(acc[mt][nt], wh[mt][ks], bl[nt]);   // wh*hl
                    mma16816(acc[mt][nt], al[mt],     bh[nt]);   // wl*hh
                }
        }

        // ---- cross-warp reduction into red [w][col][row(pad 34)] ----------
        {
            const int qr = lane >> 2;
            const int qc = (lane & 3) * 2;
#pragma unroll
            for (int mt = 0; mt < 2; mt++)
#pragma unroll
                for (int nt = 0; nt < 4; nt++) {
                    int row = mt * 16 + qr;
                    int col = nt * 8 + qc;
                    if (wid < 7) {
                        float* rp = red + wid * 1088;
                        rp[col * 34 + row]           = acc[mt][nt][0];
                        rp[(col + 1) * 34 + row]     = acc[mt][nt][1];
                        rp[col * 34 + row + 8]       = acc[mt][nt][2];
                        rp[(col + 1) * 34 + row + 8] = acc[mt][nt][3];
                    } else {  // warp 7: accumulate onto pre-staged gates
                        float* rp = red + 7 * 1088;
                        rp[col * 34 + row]           += acc[mt][nt][0];
                        rp[(col + 1) * 34 + row]     += acc[mt][nt][1];
                        rp[col * 34 + row + 8]       += acc[mt][nt][2];
                        rp[(col + 1) * 34 + row + 8] += acc[mt][nt][3];
                    }
                }
        }
        __syncthreads();

        // ---- LSTM elementwise update: thread = (unit u = wid, batch = lane)
        {
            const int u = wid, b = lane;
            float s[4];
#pragma unroll
            for (int g = 0; g < 4; g++) {
                float v = 0.f;
#pragma unroll
                for (int w2 = 0; w2 < 8; w2++)
                    v += red[w2 * 1088 + b * 34 + g * 8 + u];
                s[g] = v;
            }
            float si = 1.f / (1.f + expf(-s[0]));
            float sf = 1.f / (1.f + expf(-s[1]));
            float tg = tanhf(s[2]);
            float so = 1.f / (1.f + expf(-s[3]));
            c_reg = sf * c_reg + si * tg;
            float hn = so * tanhf(c_reg);

            int j = j0 + u;
            __nv_bfloat16 hh = __float2bfloat16(hn);
            __nv_bfloat16 hl = __float2bfloat16(hn - __bfloat162float(hh));
            hhout[b * H_ + j] = hh;
            hlout[b * H_ + j] = hl;
            if (seq_out) seq_out[(size_t)t * B_ * H_ + b * H_ + j] = hn;
            if (t == T_ - 1) g_h0[b * H_ + j] = hn;
        }

        grid_barrier();   // h(t) globally visible before step t+1 stages it
    }
}

// ---------------- head: logits + log_softmax + NLL loss ----------------------
__global__ void head_k(const float* __restrict__ fcW, const float* __restrict__ fcb,
                       const int* __restrict__ labels, float* __restrict__ out,
                       int out_size) {
    __shared__ float lg[B_ * NL_];
    __shared__ float lsum[B_];
    int tid = threadIdx.x;

    if (tid < B_ * NL_) {
        int b = tid / NL_, n = tid % NL_;
        const float4* h4 = (const float4*)(g_h0 + b * H_);
        const float4* w4 = (const float4*)(fcW + n * H_);
        float s = 0.f;
        for (int k = 0; k < H_ / 4; k++) {
            float4 a = h4[k], w = w4[k];
            s += a.x * w.x + a.y * w.y + a.z * w.z + a.w * w.w;
        }
        lg[tid] = s + fcb[n];
    }
    __syncthreads();

    if (tid < B_) {
        float m = -1e30f;
        for (int n = 0; n < NL_; n++) m = fmaxf(m, lg[tid * NL_ + n]);
        float se = 0.f;
        for (int n = 0; n < NL_; n++) se += expf(lg[tid * NL_ + n] - m);
        float lse = m + logf(se);
        int lab = labels[tid];
        lsum[tid] = -(lg[tid * NL_ + lab] - lse);
    }
    __syncthreads();

    if (tid == 0) {
        float L = 0.f;
        for (int b = 0; b < B_; b++) L += lsum[b];
        L /= (float)B_;
        if (out_size >= 1 + B_ * NL_) {
            out[0] = L;
            for (int i = 0; i < B_ * NL_; i++) out[1 + i] = lg[i];
            for (int i = 1 + B_ * NL_; i < out_size; i++) out[i] = 0.f;
        } else if (out_size == B_ * NL_) {
            for (int i = 0; i < B_ * NL_; i++) out[i] = lg[i];
        } else if (out_size >= 1) {
            out[0] = L;
            for (int i = 1; i < out_size; i++) out[i] = 0.f;
        }
    }
}

// ---------------- launch -----------------------------------------------------
extern "C" void kernel_launch(void* const* d_in, const int* in_sizes, int n_in,
                              void* d_out, int out_size) {
    const int*   x      = (const int*)  d_in[0];
    const int*   labels = (const int*)  d_in[1];
    const float* emb    = (const float*)d_in[2];
    const float* Wih    = (const float*)d_in[3];   // [2, 4096, 1024]
    const float* Whh    = (const float*)d_in[4];   // [2, 4096, 1024]
    const float* bias   = (const float*)d_in[5];   // [2, 4096]
    const float* fcW    = (const float*)d_in[6];   // [5, 1024]
    const float* fcb    = (const float*)d_in[7];   // [5]

    cudaFuncSetAttribute(lstm_tc_k, cudaFuncAttributeMaxDynamicSharedMemorySize,
                         LSTM_SMEM);

    float *seq0, *seq1, *gates;
    __nv_bfloat16 *Ah, *Al, *Wh, *Wl, *WhH, *WhL;
    cudaGetSymbolAddress((void**)&seq0,  g_seq0);
    cudaGetSymbolAddress((void**)&seq1,  g_seq1);
    cudaGetSymbolAddress((void**)&gates, g_gates);
    cudaGetSymbolAddress((void**)&Ah, g_Ah);
    cudaGetSymbolAddress((void**)&Al, g_Al);
    cudaGetSymbolAddress((void**)&Wh, g_Wh);
    cudaGetSymbolAddress((void**)&Wl, g_Wl);
    cudaGetSymbolAddress((void**)&WhH, g_WhH);
    cudaGetSymbolAddress((void**)&WhL, g_WhL);

    // 0. split weights to bf16 hi/lo (input + recurrent)
    {
        int n4 = 2 * G4_ * H_ / 4;
        split_bf16_k<<<(n4 + 255) / 256, 256>>>(Wih, Wh, Wl, n4);
        split_bf16_k<<<(n4 + 255) / 256, 256>>>(Whh, WhH, WhL, n4);
    }
    // 1. embed -> g_seq0 (time-major [T, B, H])
    embed_k<<<T_ * B_, 256>>>(x, emb);

    for (int l = 0; l < 2; l++) {
        const float* A = (l == 0) ? seq0 : seq1;
        // 2a. split A to bf16 hi/lo
        int n4 = T_ * B_ * H_ / 4;
        split_bf16_k<<<(n4 + 255) / 256, 256>>>(A, Ah, Al, n4);
        // 2b. tensor-core input GEMM
        gemm_mma_k<<<dim3(G4_ / 128, (T_ * B_) / 128), 256>>>(
            Ah, Al, Wh + (size_t)l * G4_ * H_, Wl + (size_t)l * G4_ * H_,
            bias + (size_t)l * G4_, gates);
        // 3. tensor-core persistent recurrence
        float* seq_out = (l == 0) ? seq1 : nullptr;
        lstm_tc_k<<<NBLK, 256, LSTM_SMEM>>>(
            WhH + (size_t)l * G4_ * H_, WhL + (size_t)l * G4_ * H_,
            gates, seq_out);
    }

    // 4. head
    head_k<<<1, 256>>>(fcW, fcb, labels, (float*)d_out, out_size);
}